// round 6
// baseline (speedup 1.0000x reference)
#include <cuda_runtime.h>
#include <cuda_bf16.h>
#include <math_constants.h>
#include <cstdint>

#define NB 8192
#define GRID 1024            // 1024 CTAs x 4 warps x 2 samples = 8192
#define THREADS 128
#define STAGES 4             // per-warp pipeline depth (4 x 4KB = one sample in flight)
#define CHUNK_BYTES 4096     // 1024 floats = 16 rows
#define FP_SCALE 32768.0

__device__ unsigned long long g_acc;
__device__ unsigned int g_done;

// Packed fp32x2 ops (Blackwell FFMA2 path — PTX-only)
#define ADDX2(d, a, b)    asm("add.rn.f32x2 %0,%1,%2;"    : "=l"(d) : "l"(a), "l"(b))
#define FMAX2(d, a, b, c) asm("fma.rn.f32x2 %0,%1,%2,%3;" : "=l"(d) : "l"(a), "l"(b), "l"(c))
#define PACKX2(d, lo, hi) asm("mov.b64 %0,{%1,%2};"       : "=l"(d) : "f"(lo), "f"(hi))
#define UNPACKX2(lo, hi, d) asm("mov.b64 {%0,%1},%2;"     : "=f"(lo), "=f"(hi) : "l"(d))

__device__ __forceinline__ uint32_t smem_u32(const void* p) {
    return (uint32_t)__cvta_generic_to_shared(p);
}
__device__ __forceinline__ void mbar_init(uint32_t a, uint32_t cnt) {
    asm volatile("mbarrier.init.shared.b64 [%0], %1;" :: "r"(a), "r"(cnt) : "memory");
}
__device__ __forceinline__ void mbar_expect_tx(uint32_t a, uint32_t bytes) {
    asm volatile("mbarrier.arrive.expect_tx.shared.b64 _, [%0], %1;"
                 :: "r"(a), "r"(bytes) : "memory");
}
__device__ __forceinline__ void bulk_ld(uint32_t dst, const void* src, uint32_t mbar) {
    asm volatile("cp.async.bulk.shared::cta.global.mbarrier::complete_tx::bytes"
                 " [%0], [%1], %2, [%3];"
                 :: "r"(dst), "l"(src), "r"((uint32_t)CHUNK_BYTES), "r"(mbar) : "memory");
}
__device__ __forceinline__ void mbar_wait(uint32_t a, uint32_t parity) {
    asm volatile(
        "{\n\t.reg .pred P;\n"
        "W_%=:\n\t"
        "mbarrier.try_wait.parity.acquire.cta.shared::cta.b64 P, [%0], %1, 0x989680;\n\t"
        "@P bra D_%=;\n\t"
        "bra W_%=;\n"
        "D_%=:\n\t}"
        :: "r"(a), "r"(parity) : "memory");
}

__global__ void __launch_bounds__(THREADS)
loss_kernel(const float* __restrict__ x, float* __restrict__ out) {
    extern __shared__ char smem[];
    // layout: [0,128): 16 mbarriers (8B each); [128,144): wloss; [1024,+64KB): stages
    unsigned long long* mbar_arr = reinterpret_cast<unsigned long long*>(smem);
    float* wloss = reinterpret_cast<float*>(smem + 128);
    float4* stages = reinterpret_cast<float4*>(smem + 1024);

    const int t = threadIdx.x;
    const int w = t >> 5;
    const int l = t & 31;
    const int warp_g = blockIdx.x * 4 + w;

    if (t == 0) {
        #pragma unroll
        for (int i = 0; i < 16; ++i) mbar_init(smem_u32(&mbar_arr[i]), 1u);
    }
    __syncthreads();

    const uint32_t mb0 = smem_u32(&mbar_arr[w * STAGES]);
    // this warp's 4 stages, each 256 float4 (4KB)
    float4* const stg = stages + (size_t)w * STAGES * 256;
    const uint32_t stg0 = smem_u32(stg);

    // prime: sample0 = warp_g, its 4 chunks into stages 0..3
    if (l == 0) {
        #pragma unroll
        for (int s = 0; s < STAGES; ++s) {
            mbar_expect_tx(mb0 + s * 8, CHUNK_BYTES);
            bulk_ld(stg0 + s * CHUNK_BYTES,
                    x + (size_t)warp_g * 4096 + s * 1024, mb0 + s * 8);
        }
    }

    const unsigned long long C23 = 0x4040000040000000ULL; // (2,3)
    const unsigned long long C49 = 0x4110000040800000ULL; // (4,9)

    float acc_loss = 0.f;

    #pragma unroll
    for (int smp = 0; smp < 2; ++smp) {
        const int b = warp_g + smp * 4096;

        unsigned long long s0p = 0, Up = 0, Vp = 0, mp1 = 0, mp2 = 0;
        float sy = 0.f;
        float bv = -CUDART_INF_F;
        int   bi = 0x7fffffff;

        #pragma unroll
        for (int cq = 0; cq < 4; ++cq) {          // chunk within sample
            mbar_wait(mb0 + cq * 8, (uint32_t)smp);   // stage cq, parity = reuse count

            // front-batch 8 LDS.128 (conflict-free: lanes read 512B contiguous)
            const float4* sp = stg + cq * 256 + l;
            float4 v[8];
            #pragma unroll
            for (int it = 0; it < 8; ++it) v[it] = sp[it * 32];

            #pragma unroll
            for (int it = 0; it < 8; ++it) {
                const int c = cq * 8 + it;        // quad-row counter 0..31 (as R2)
                const float X = v[it].x, Y = v[it].y, Z = v[it].z, W = v[it].w;
                unsigned long long p0, p1, lsp;
                PACKX2(p0, X, Y);
                PACKX2(p1, Z, W);
                ADDX2(lsp, p0, p1);
                ADDX2(s0p, s0p, lsp);
                ADDX2(Up,  Up,  s0p);
                ADDX2(Vp,  Vp,  Up);
                FMAX2(mp1, p1, C23, mp1);
                FMAX2(mp2, p1, C49, mp2);
                sy += Y;

                const float m = fmaxf(fmaxf(X, Y), fmaxf(Z, W));
                if (m > bv) {                     // first-max, ascending indices
                    bv = m;
                    const int cc = (m == X) ? 0 : ((m == Y) ? 1 : ((m == Z) ? 2 : 3));
                    bi = ((c * 32 + l) << 2) + cc;
                }
            }

            // all lanes consumed this stage -> safe to refill with sample1's chunk
            __syncwarp();
            if (smp == 0 && l == 0) {
                mbar_expect_tx(mb0 + cq * 8, CHUNK_BYTES);
                bulk_ld(stg0 + cq * CHUNK_BYTES,
                        x + (size_t)(warp_g + 4096) * 4096 + cq * 1024,
                        mb0 + cq * 8);
            }
        }

        // ---- fold packed accumulators (identical to R2, verified exact) ----
        float s0lo, s0hi, Ulo, Uhi, Vlo, Vhi, m1lo, m1hi, m2lo, m2hi;
        UNPACKX2(s0lo, s0hi, s0p);
        UNPACKX2(Ulo, Uhi, Up);
        UNPACKX2(Vlo, Vhi, Vp);
        UNPACKX2(m1lo, m1hi, mp1);
        UNPACKX2(m2lo, m2hi, mp2);

        float s0 = s0lo + s0hi;
        const float cU = Ulo + Uhi;
        const float cV = Vlo + Vhi;
        const float sc1 = fmaf(32.f, s0, -cU);                          // sum c*ls
        const float sc2 = fmaf(1024.f, s0, fmaf(-65.f, cU, 2.f * cV));  // sum c^2*ls
        const float jh = (float)(l >> 4);
        float sj  = fmaf(2.f, sc1, jh * s0);
        float sjj = fmaf(4.f, sc2, fmaf(4.f * jh, sc1, jh * s0));       // jh^2 == jh
        const float m1 = sy + m1lo + m1hi;
        const float m2 = sy + m2lo + m2hi;
        const float k0 = (float)((l & 15) << 2);
        float sk  = fmaf(k0, s0, m1);
        const float skk = fmaf(k0 * k0, s0, fmaf(2.f * k0, m1, m2));
        float sq = sjj + skk;

        #pragma unroll
        for (int off = 16; off > 0; off >>= 1) {
            s0 += __shfl_down_sync(0xffffffffu, s0, off);
            sj += __shfl_down_sync(0xffffffffu, sj, off);
            sk += __shfl_down_sync(0xffffffffu, sk, off);
            sq += __shfl_down_sync(0xffffffffu, sq, off);
            const float ov = __shfl_down_sync(0xffffffffu, bv, off);
            const int   oi = __shfl_down_sync(0xffffffffu, bi, off);
            if (ov > bv || (ov == bv && oi < bi)) { bv = ov; bi = oi; }
        }

        if (l == 0) {
            const float mx = (float)(bi >> 6);
            const float my = (float)(bi & 63);
            acc_loss += (mx * mx + my * my) * s0
                      - 2.f * mx * sj - 2.f * my * sk + sq;
        }
        (void)b;
    }

    if (l == 0) wloss[w] = acc_loss;
    __syncthreads();

    if (t == 0) {
        const double tot = (double)wloss[0] + (double)wloss[1]
                         + (double)wloss[2] + (double)wloss[3];
        const long long q = llrint(tot * FP_SCALE);
        atomicAdd(&g_acc, (unsigned long long)q);
        __threadfence();
        const unsigned int n = atomicAdd(&g_done, 1u);
        if (n == GRID - 1u) {
            const long long totq = (long long)atomicExch(&g_acc, 0ULL);
            g_done = 0;
            out[0] = (float)((double)totq / FP_SCALE);
        }
    }
}

extern "C" void kernel_launch(void* const* d_in, const int* in_sizes, int n_in,
                              void* d_out, int out_size) {
    const float* x = (const float*)d_in[0];
    float* out = (float*)d_out;
    static int configured = 0;
    if (!configured) {
        cudaFuncSetAttribute(loss_kernel,
                             cudaFuncAttributeMaxDynamicSharedMemorySize,
                             1024 + 4 * STAGES * CHUNK_BYTES);
        configured = 1;
    }
    loss_kernel<<<GRID, THREADS, 1024 + 4 * STAGES * CHUNK_BYTES>>>(x, out);
}

// round 7
// speedup vs baseline: 1.0135x; 1.0135x over previous
#include <cuda_runtime.h>
#include <cuda_bf16.h>
#include <math_constants.h>
#include <cstdint>

#define NB 8192
#define GRID 2048            // 2048 CTAs x 4 samples = 8192
#define THREADS 128
#define STG_BYTES 16384      // one sample per stage
#define NSTAGE 3
#define MBAR_OFF (NSTAGE * STG_BYTES)          // 49152
#define SLOT_OFF (MBAR_OFF + 32)               // 49184
#define SMEM_TOTAL (SLOT_OFF + 2 * 4 * 8 * 4)  // + slots[2][4][8] floats
#define FP_SCALE 32768.0

__device__ unsigned long long g_acc;
__device__ unsigned int g_done;

// Packed fp32x2 ops (Blackwell FFMA2 path — PTX-only)
#define ADDX2(d, a, b)    asm("add.rn.f32x2 %0,%1,%2;"    : "=l"(d) : "l"(a), "l"(b))
#define FMAX2(d, a, b, c) asm("fma.rn.f32x2 %0,%1,%2,%3;" : "=l"(d) : "l"(a), "l"(b), "l"(c))
#define PACKX2(d, lo, hi) asm("mov.b64 %0,{%1,%2};"       : "=l"(d) : "f"(lo), "f"(hi))
#define UNPACKX2(lo, hi, d) asm("mov.b64 {%0,%1},%2;"     : "=f"(lo), "=f"(hi) : "l"(d))

__device__ __forceinline__ uint32_t smem_u32(const void* p) {
    return (uint32_t)__cvta_generic_to_shared(p);
}
__device__ __forceinline__ void mbar_init(uint32_t a, uint32_t cnt) {
    asm volatile("mbarrier.init.shared.b64 [%0], %1;" :: "r"(a), "r"(cnt) : "memory");
}
__device__ __forceinline__ void mbar_expect_tx(uint32_t a, uint32_t bytes) {
    asm volatile("mbarrier.arrive.expect_tx.shared.b64 _, [%0], %1;"
                 :: "r"(a), "r"(bytes) : "memory");
}
__device__ __forceinline__ void bulk_ld(uint32_t dst, const void* src, uint32_t mbar) {
    asm volatile("cp.async.bulk.shared::cta.global.mbarrier::complete_tx::bytes"
                 " [%0], [%1], %2, [%3];"
                 :: "r"(dst), "l"(src), "r"((uint32_t)STG_BYTES), "r"(mbar) : "memory");
}
__device__ __forceinline__ void mbar_wait(uint32_t a, uint32_t parity) {
    asm volatile(
        "{\n\t.reg .pred P;\n"
        "W_%=:\n\t"
        "mbarrier.try_wait.parity.acquire.cta.shared::cta.b64 P, [%0], %1, 0x989680;\n\t"
        "@P bra D_%=;\n\t"
        "bra W_%=;\n"
        "D_%=:\n\t}"
        :: "r"(a), "r"(parity) : "memory");
}

__global__ void __launch_bounds__(THREADS)
loss_kernel(const float* __restrict__ x, float* __restrict__ out) {
    extern __shared__ char smem[];
    float* slots = reinterpret_cast<float*>(smem + SLOT_OFF); // [2][4][8]

    const int t = threadIdx.x;
    const int w = t >> 5;
    const int l = t & 31;
    const int b0 = blockIdx.x * 4;

    const uint32_t mb = smem_u32(smem + MBAR_OFF);
    const uint32_t st = smem_u32(smem);

    if (t == 0) {
        #pragma unroll
        for (int i = 0; i < NSTAGE; ++i) mbar_init(mb + i * 8, 1u);
    }
    __syncthreads();

    // Prime: samples b0..b0+2 into stages 0..2
    if (t == 0) {
        #pragma unroll
        for (int s = 0; s < NSTAGE; ++s) {
            mbar_expect_tx(mb + s * 8, STG_BYTES);
            bulk_ld(st + s * STG_BYTES, x + (size_t)(b0 + s) * 4096, mb + s * 8);
        }
    }

    const unsigned long long C23 = 0x4040000040000000ULL; // (2,3)
    const unsigned long long C49 = 0x4110000040800000ULL; // (4,9)

    double loss_acc = 0.0;   // live only on t==0

    #pragma unroll
    for (int smp = 0; smp < 4; ++smp) {
        const int stage  = smp % NSTAGE;
        const int parity = smp / NSTAGE;   // 0,0,0,1

        mbar_wait(mb + stage * 8, (uint32_t)parity);

        // CTA-cooperative consume: thread t reads float4 q = it*128 + t
        const float4* sp = reinterpret_cast<const float4*>(smem + stage * STG_BYTES) + t;
        float4 v[8];
        #pragma unroll
        for (int it = 0; it < 8; ++it) v[it] = sp[it * 128];

        unsigned long long s0p = 0, Up = 0, Vp = 0, mp1 = 0, mp2 = 0;
        float sy = 0.f;
        float bv = -CUDART_INF_F;
        int   bi = 0x7fffffff;

        #pragma unroll
        for (int it = 0; it < 8; ++it) {
            const float X = v[it].x, Y = v[it].y, Z = v[it].z, W = v[it].w;
            unsigned long long p0, p1, lsp;
            PACKX2(p0, X, Y);
            PACKX2(p1, Z, W);
            ADDX2(lsp, p0, p1);
            ADDX2(s0p, s0p, lsp);
            ADDX2(Up,  Up,  s0p);
            ADDX2(Vp,  Vp,  Up);
            FMAX2(mp1, p1, C23, mp1);
            FMAX2(mp2, p1, C49, mp2);
            sy += Y;

            const float m = fmaxf(fmaxf(X, Y), fmaxf(Z, W));
            if (m > bv) {     // first-max; within-thread q ascends with it
                bv = m;
                const int cc = (m == X) ? 0 : ((m == Y) ? 1 : ((m == Z) ? 2 : 3));
                bi = ((it * 128 + t) << 2) + cc;
            }
        }

        // fold packed accumulators (prefix trick, T = 8 iterations)
        float s0lo, s0hi, Ulo, Uhi, Vlo, Vhi, m1lo, m1hi, m2lo, m2hi;
        UNPACKX2(s0lo, s0hi, s0p);
        UNPACKX2(Ulo, Uhi, Up);
        UNPACKX2(Vlo, Vhi, Vp);
        UNPACKX2(m1lo, m1hi, mp1);
        UNPACKX2(m2lo, m2hi, mp2);

        float s0 = s0lo + s0hi;
        const float cU = Ulo + Uhi;
        const float cV = Vlo + Vhi;
        const float si1 = fmaf(8.f, s0, -cU);                        // sum it*ls
        const float si2 = fmaf(64.f, s0, fmaf(-17.f, cU, 2.f * cV)); // sum it^2*ls
        // j = 8*it + jb,  jb = t>>4
        const float jb = (float)(t >> 4);
        float sj  = fmaf(8.f, si1, jb * s0);
        float sjj = fmaf(64.f, si2, fmaf(16.f * jb, si1, jb * jb * s0));
        // k = k0 + c,  k0 = (t&15)*4 thread-constant
        const float m1 = sy + m1lo + m1hi;
        const float m2 = sy + m2lo + m2hi;
        const float k0 = (float)((t & 15) << 2);
        float sk  = fmaf(k0, s0, m1);
        const float skk = fmaf(k0 * k0, s0, fmaf(2.f * k0, m1, m2));
        float sq = sjj + skk;

        // warp reduce
        #pragma unroll
        for (int off = 16; off > 0; off >>= 1) {
            s0 += __shfl_down_sync(0xffffffffu, s0, off);
            sj += __shfl_down_sync(0xffffffffu, sj, off);
            sk += __shfl_down_sync(0xffffffffu, sk, off);
            sq += __shfl_down_sync(0xffffffffu, sq, off);
            const float ov = __shfl_down_sync(0xffffffffu, bv, off);
            const int   oi = __shfl_down_sync(0xffffffffu, bi, off);
            if (ov > bv || (ov == bv && oi < bi)) { bv = ov; bi = oi; }
        }

        float* slot = slots + (smp & 1) * 32 + w * 8;
        if (l == 0) {
            slot[0] = s0; slot[1] = sj; slot[2] = sk; slot[3] = sq;
            slot[4] = bv; reinterpret_cast<int*>(slot)[5] = bi;
        }
        __syncthreads();   // slots ready AND all LDS of this stage consumed

        if (t == 0) {
            // refill drained stage with this CTA's 4th sample
            if (smp == 0) {
                mbar_expect_tx(mb + 0, STG_BYTES);
                bulk_ld(st + 0, x + (size_t)(b0 + 3) * 4096, mb + 0);
            }
            const float* sl = slots + (smp & 1) * 32;
            float fs0 = sl[0], fsj = sl[1], fsk = sl[2], fsq = sl[3];
            float fbv = sl[4]; int fbi = reinterpret_cast<const int*>(sl)[5];
            #pragma unroll
            for (int ww = 1; ww < 4; ++ww) {
                const float* s2 = sl + ww * 8;
                fs0 += s2[0]; fsj += s2[1]; fsk += s2[2]; fsq += s2[3];
                const float ov = s2[4];
                const int   oi = reinterpret_cast<const int*>(s2)[5];
                if (ov > fbv || (ov == fbv && oi < fbi)) { fbv = ov; fbi = oi; }
            }
            const float mx = (float)(fbi >> 6);
            const float my = (float)(fbi & 63);
            loss_acc += (double)((mx * mx + my * my) * fs0
                                 - 2.f * mx * fsj - 2.f * my * fsk + fsq);
        }
    }

    if (t == 0) {
        const long long q = llrint(loss_acc * FP_SCALE);
        atomicAdd(&g_acc, (unsigned long long)q);
        __threadfence();
        const unsigned int n = atomicAdd(&g_done, 1u);
        if (n == GRID - 1u) {
            const long long totq = (long long)atomicExch(&g_acc, 0ULL);
            g_done = 0;
            out[0] = (float)((double)totq / FP_SCALE);
        }
    }
}

extern "C" void kernel_launch(void* const* d_in, const int* in_sizes, int n_in,
                              void* d_out, int out_size) {
    const float* x = (const float*)d_in[0];
    float* out = (float*)d_out;
    static int configured = 0;
    if (!configured) {
        cudaFuncSetAttribute(loss_kernel,
                             cudaFuncAttributeMaxDynamicSharedMemorySize,
                             SMEM_TOTAL);
        configured = 1;
    }
    loss_kernel<<<GRID, THREADS, SMEM_TOTAL>>>(x, out);
}

// round 8
// speedup vs baseline: 1.1509x; 1.1356x over previous
#include <cuda_runtime.h>
#include <cuda_bf16.h>
#include <math_constants.h>

#define NB 8192
#define GRID 1024           // 1024 CTAs x 4 warps x 2 samples = 8192 samples
#define THREADS 128
#define FP_SCALE 32768.0    // 2^15 fixed point (deterministic integer accumulation)

__device__ unsigned long long g_acc;
__device__ unsigned int g_done;

// Packed fp32x2 ops (Blackwell FFMA2 path — PTX-only)
#define ADDX2(d, a, b)    asm("add.rn.f32x2 %0,%1,%2;"    : "=l"(d) : "l"(a), "l"(b))
#define FMAX2(d, a, b, c) asm("fma.rn.f32x2 %0,%1,%2,%3;" : "=l"(d) : "l"(a), "l"(b), "l"(c))
#define PACKX2(d, lo, hi) asm("mov.b64 %0,{%1,%2};"       : "=l"(d) : "f"(lo), "f"(hi))
#define UNPACKX2(lo, hi, d) asm("mov.b64 {%0,%1},%2;"     : "=f"(lo), "=f"(hi) : "l"(d))

// 128-bit load with 256B L2 prefetch granularity: halves the number of DRAM
// refills (and L2 MSHR occupancy) per byte for a fully-streamed tensor.
__device__ __forceinline__ float4 ld4_pf(const float4* p) {
    float4 v;
    asm volatile("ld.global.nc.L2::256B.v4.f32 {%0,%1,%2,%3}, [%4];"
                 : "=f"(v.x), "=f"(v.y), "=f"(v.z), "=f"(v.w) : "l"(p));
    return v;
}

__global__ void __launch_bounds__(THREADS, 7)
loss_kernel(const float* __restrict__ x, float* __restrict__ out) {
    const int t = threadIdx.x;
    const int w = t >> 5;
    const int l = t & 31;
    const int warp_g = blockIdx.x * 4 + w;

    __shared__ float wloss[4];

    const unsigned long long C23 = 0x4040000040000000ULL; // (2.0f, 3.0f)
    const unsigned long long C49 = 0x4110000040800000ULL; // (4.0f, 9.0f)

    float acc_loss = 0.f;

    #pragma unroll
    for (int s = 0; s < 2; ++s) {
        const int b = warp_g + s * 4096;
        const float4* __restrict__ xp =
            reinterpret_cast<const float4*>(x) + (size_t)b * 1024 + l;

        // Packed accumulators (bit-zero == (0.f, 0.f))
        unsigned long long s0p = 0, Up = 0, Vp = 0, mp1 = 0, mp2 = 0;
        float sy = 0.f;
        float bv = -CUDART_INF_F;
        int   bi = 0x7fffffff;

        // 4-deep rolling prefetch over 32 chunks (8 groups of 4)
        float4 buf[4];
        #pragma unroll
        for (int i = 0; i < 4; ++i) buf[i] = ld4_pf(&xp[i * 32]);

        #pragma unroll
        for (int g = 0; g < 8; ++g) {
            float4 nbuf[4];
            if (g < 7) {
                #pragma unroll
                for (int i = 0; i < 4; ++i)
                    nbuf[i] = ld4_pf(&xp[(g + 1) * 128 + i * 32]);
            }
            #pragma unroll
            for (int i = 0; i < 4; ++i) {
                const int c = g * 4 + i;            // chunk index 0..31
                const float X = buf[i].x, Y = buf[i].y, Z = buf[i].z, W = buf[i].w;
                unsigned long long p0, p1, lsp;
                PACKX2(p0, X, Y);
                PACKX2(p1, Z, W);
                ADDX2(lsp, p0, p1);                 // (X+Z, Y+W)
                ADDX2(s0p, s0p, lsp);               // running sum
                ADDX2(Up,  Up,  s0p);               // prefix of prefix -> c-moment
                ADDX2(Vp,  Vp,  Up);                // -> c^2-moment
                FMAX2(mp1, p1, C23, mp1);           // 2Z + 3W
                FMAX2(mp2, p1, C49, mp2);           // 4Z + 9W
                sy += Y;                            // Y coeff is 1 in both m1,m2

                const float m = fmaxf(fmaxf(X, Y), fmaxf(Z, W));
                if (m > bv) {                       // first-max: strict '>', c ascending
                    bv = m;
                    const int cc = (m == X) ? 0 : ((m == Y) ? 1 : ((m == Z) ? 2 : 3));
                    bi = ((c * 32 + l) << 2) + cc;
                }
            }
            #pragma unroll
            for (int i = 0; i < 4; ++i) buf[i] = nbuf[i];
        }

        // ---- fold packed accumulators ----
        float s0lo, s0hi, Ulo, Uhi, Vlo, Vhi, m1lo, m1hi, m2lo, m2hi;
        UNPACKX2(s0lo, s0hi, s0p);
        UNPACKX2(Ulo, Uhi, Up);
        UNPACKX2(Vlo, Vhi, Vp);
        UNPACKX2(m1lo, m1hi, mp1);
        UNPACKX2(m2lo, m2hi, mp2);

        float s0 = s0lo + s0hi;
        const float cU = Ulo + Uhi;
        const float cV = Vlo + Vhi;
        // Sum c*ls = 32*s0 - U ;  Sum c^2*ls = 1024*s0 - 65*U + 2*V
        const float sc1 = fmaf(32.f, s0, -cU);
        const float sc2 = fmaf(1024.f, s0, fmaf(-65.f, cU, 2.f * cV));
        // j = 2c + jh
        const float jh = (float)(l >> 4);
        float sj  = fmaf(2.f, sc1, jh * s0);
        float sjj = fmaf(4.f, sc2, fmaf(4.f * jh, sc1, jh * s0)); // jh^2 == jh
        // k = k0 + cc  (k0 thread-constant)
        const float m1 = sy + m1lo + m1hi;
        const float m2 = sy + m2lo + m2hi;
        const float k0 = (float)((l & 15) << 2);
        float sk  = fmaf(k0, s0, m1);
        const float skk = fmaf(k0 * k0, s0, fmaf(2.f * k0, m1, m2));
        float sq = sjj + skk;

        // ---- warp-only reduction ----
        #pragma unroll
        for (int off = 16; off > 0; off >>= 1) {
            s0 += __shfl_down_sync(0xffffffffu, s0, off);
            sj += __shfl_down_sync(0xffffffffu, sj, off);
            sk += __shfl_down_sync(0xffffffffu, sk, off);
            sq += __shfl_down_sync(0xffffffffu, sq, off);
            const float ov = __shfl_down_sync(0xffffffffu, bv, off);
            const int   oi = __shfl_down_sync(0xffffffffu, bi, off);
            if (ov > bv || (ov == bv && oi < bi)) { bv = ov; bi = oi; }
        }

        if (l == 0) {
            const float mx = (float)(bi >> 6);
            const float my = (float)(bi & 63);
            acc_loss += (mx * mx + my * my) * s0
                      - 2.f * mx * sj
                      - 2.f * my * sk
                      + sq;
        }
    }

    if (l == 0) wloss[w] = acc_loss;
    __syncthreads();

    if (t == 0) {
        const double tot = (double)wloss[0] + (double)wloss[1]
                         + (double)wloss[2] + (double)wloss[3];
        const long long q = llrint(tot * FP_SCALE);
        atomicAdd(&g_acc, (unsigned long long)q);
        __threadfence();
        const unsigned int n = atomicAdd(&g_done, 1u);
        if (n == GRID - 1u) {
            const long long totq = (long long)atomicExch(&g_acc, 0ULL);
            g_done = 0;
            out[0] = (float)((double)totq / FP_SCALE);
        }
    }
}

extern "C" void kernel_launch(void* const* d_in, const int* in_sizes, int n_in,
                              void* d_out, int out_size) {
    const float* x = (const float*)d_in[0];
    float* out = (float*)d_out;
    loss_kernel<<<GRID, THREADS>>>(x, out);
}